// round 14
// baseline (speedup 1.0000x reference)
#include <cuda_runtime.h>
#include <cstdint>

// SpectralConv1d via mma.sync (HMMA) bf16 2-way-split GEMM. Round 14.
// R14 = R12 compute (m32 warp tile, transient B regs) + triple-buffered
//       cp.async ring with earliest-possible fill issue (2-tile lead).

#define THREADS 256
#define KT      8
#define TROWS   32                      // rows per tile
#define TILES   4                       // 128 rows per CTA
#define RS      258                     // u64 per stage row (16B-aligned pairs)
#define BUFB    (TROWS * RS * 8)        // 66048 bytes per buffer
#define NBUF    3
#define SMEM_BYTES (NBUF * BUFB)        // 198144

__device__ unsigned long long gB[8 * 16384];  // [kgi][md][s][ks][j][lane][2] u64

__device__ __forceinline__ unsigned smem_u32(const void* p) {
    unsigned a;
    asm("{ .reg .u64 t; cvta.to.shared.u64 t, %1; cvt.u32.u64 %0, t; }" : "=r"(a) : "l"(p));
    return a;
}
__device__ __forceinline__ unsigned cvt2bf(float lo, float hi) {
    unsigned r;
    asm("cvt.rn.bf16x2.f32 %0, %1, %2;" : "=r"(r) : "f"(hi), "f"(lo));
    return r;
}
__device__ __forceinline__ unsigned long long pack2(float lo, float hi) {
    unsigned long long r;
    asm("mov.b64 %0, {%1, %2};" : "=l"(r) : "f"(lo), "f"(hi));
    return r;
}
__device__ __forceinline__ unsigned long long lds64(unsigned a) {
    unsigned long long v;
    asm volatile("ld.shared.b64 %0, [%1];" : "=l"(v) : "r"(a));
    return v;
}
__device__ __forceinline__ void sts64(unsigned a, unsigned long long v) {
    asm volatile("st.shared.b64 [%0], %1;" :: "r"(a), "l"(v));
}
__device__ __forceinline__ void cp_async16(unsigned dst, const void* src) {
    asm volatile("cp.async.cg.shared.global [%0], [%1], 16;\n" :: "r"(dst), "l"(src));
}
__device__ __forceinline__ void cp_commit() { asm volatile("cp.async.commit_group;\n"); }
__device__ __forceinline__ void cp_wait0()  { asm volatile("cp.async.wait_group 0;\n"); }
__device__ __forceinline__ void cp_wait1()  { asm volatile("cp.async.wait_group 1;\n"); }
__device__ __forceinline__ void cp_wait2()  { asm volatile("cp.async.wait_group 2;\n"); }
__device__ __forceinline__ void mma16816(float* c, const unsigned* a,
                                         unsigned b0, unsigned b1) {
    asm volatile(
        "mma.sync.aligned.m16n8k16.row.col.f32.bf16.bf16.f32 "
        "{%0,%1,%2,%3}, {%4,%5,%6,%7}, {%8,%9}, {%0,%1,%2,%3};"
        : "+f"(c[0]), "+f"(c[1]), "+f"(c[2]), "+f"(c[3])
        : "r"(a[0]), "r"(a[1]), "r"(a[2]), "r"(a[3]), "r"(b0), "r"(b1));
}

// ---- prep: B fragments, lane-consecutive layout (same as R10-R13) ----
__global__ void __launch_bounds__(256)
spectral_prepB_kernel(const float* __restrict__ W)
{
    const int kgi = blockIdx.x;                 // 0..7
    const int kbase = kgi * KT;
    unsigned* dst = reinterpret_cast<unsigned*>(gB + kgi * 16384);

    #pragma unroll
    for (int it = 0; it < 32; ++it) {
        int idx = threadIdx.x + it * 256;       // 8192 = (o,i,md)
        int md = idx & 7, i = (idx >> 3) & 31, o = idx >> 8;
        float2 wv = *reinterpret_cast<const float2*>(
            W + (size_t)o * 4096 + i * 128 + (size_t)(kbase + md) * 2);
        unsigned ph = cvt2bf(wv.x, wv.y);       // low=wr_h, high=wi_h
        float wrh = __uint_as_float(ph << 16);
        float wih = __uint_as_float(ph & 0xFFFF0000u);
        unsigned pl = cvt2bf(wv.x - wrh, wv.y - wih);
        const int ks = i >> 3, half = (i >> 2) & 1, t4 = i & 3;
        #pragma unroll
        for (int s = 0; s < 2; ++s) {
            unsigned p = s ? pl : ph;
            #pragma unroll
            for (int c = 0; c < 2; ++c) {       // n = 2o + c
                int n = 2 * o + c;
                int gid = n & 7, nt = n >> 3, j = nt >> 1, wsel = nt & 1;
                unsigned u64i =
                    (unsigned)(((((md * 2 + s) * 4 + ks) * 4 + j) * 32
                                + (gid * 4 + t4)) * 2 + wsel);
                unsigned val = c ? ((p >> 16) | (p << 16))    // (wi, wr)
                                 : (p ^ 0x80000000u);         // (wr, -wi)
                dst[u64i * 2 + half] = val;
            }
        }
    }
}

// ---- main ----
__global__ void __launch_bounds__(THREADS, 1)
spectral_r14_kernel(const float* __restrict__ X,
                    float* __restrict__ O)
{
    extern __shared__ char smem[];
    const unsigned sb = smem_u32(smem);

    const int tid  = threadIdx.x;
    const int lane = tid & 31;
    const int md   = tid >> 5;                  // warp == mode
    const int gid  = lane >> 2;
    const int t4   = lane & 3;
    const int kgi  = blockIdx.y;
    const int kg   = kgi * KT;
    const long rowBase = (long)blockIdx.x * (TROWS * TILES);

    // fill tile t (raw fp32 pairs; 16B = 2 modes, slot-swizzled), L2-only
    auto fill = [&](int t) {
        const unsigned buf = sb + (unsigned)(t % NBUF) * BUFB;
        const float* base = X + (rowBase + (long)t * TROWS) * 4096 + (size_t)kg * 2;
        #pragma unroll
        for (int it = 0; it < 16; ++it) {
            int idx = tid + it * THREADS;       // 4096 = (row, i, md2)
            int md2 = idx & 3, i = (idx >> 2) & 31, row = idx >> 7;
            cp_async16(buf + (unsigned)(row * RS + i * 8 + ((2 * md2) ^ (i & 6))) * 8,
                       base + (size_t)row * 4096 + i * 128 + md2 * 4);
        }
        cp_commit();
    };

    fill(0); fill(1); fill(2);

    const unsigned long long* Bk = gB + kgi * 16384;

    #pragma unroll 1
    for (int t = 0; t < TILES; ++t) {
        const unsigned cur = sb + (unsigned)(t % NBUF) * BUFB;
        char* curp = smem + (size_t)(t % NBUF) * BUFB;

        // fill(t) must be complete; keep newer fills in flight
        if (t == 0) cp_wait2();
        else if (t == TILES - 1) cp_wait0();
        else cp_wait1();
        __syncthreads();   // also guarantees tile t-3's smem reads are done

        // earliest issue: buffer (t+2)%NBUF was freed by tile t-1's stores
        if (t >= 1 && t + 2 < TILES) fill(t + 2);

        float acc[2][8][4];
        #pragma unroll
        for (int mt = 0; mt < 2; ++mt)
            #pragma unroll
            for (int nt = 0; nt < 8; ++nt)
                #pragma unroll
                for (int q = 0; q < 4; ++q) acc[mt][nt][q] = 0.0f;

        #pragma unroll
        for (int ks = 0; ks < 4; ++ks) {
            // B fragments: lane-consecutive LDG.128 (L1-resident), transient
            const ulonglong2* bh2 = reinterpret_cast<const ulonglong2*>(
                Bk + (size_t)((((md * 2 + 0) * 4 + ks) * 4) * 32 + lane) * 2);
            const ulonglong2* bl2 = reinterpret_cast<const ulonglong2*>(
                Bk + (size_t)((((md * 2 + 1) * 4 + ks) * 4) * 32 + lane) * 2);
            ulonglong2 BH[4], BL[4];
            #pragma unroll
            for (int j = 0; j < 4; ++j) { BH[j] = bh2[j * 32]; BL[j] = bl2[j * 32]; }

            // A fragments: raw fp32 LDS.64 + split-at-use
            unsigned ah[2][4], al[2][4];
            #pragma unroll
            for (int mt = 0; mt < 2; ++mt)
                #pragma unroll
                for (int j = 0; j < 4; ++j) {
                    int row = mt * 16 + gid + (j & 1) * 8;
                    int i   = t4 + (j >> 1) * 4 + 8 * ks;
                    unsigned long long v = lds64(
                        cur + (unsigned)(row * RS + i * 8 + (md ^ (i & 6))) * 8);
                    float xr, xi;
                    asm("mov.b64 {%0,%1}, %2;" : "=f"(xr), "=f"(xi) : "l"(v));
                    unsigned ph = cvt2bf(xr, xi);
                    float xrh = __uint_as_float(ph << 16);
                    float xih = __uint_as_float(ph & 0xFFFF0000u);
                    ah[mt][j] = ph;
                    al[mt][j] = cvt2bf(xr - xrh, xi - xih);
                }

            #pragma unroll
            for (int nt = 0; nt < 8; ++nt) {
                unsigned long long bh = (nt & 1) ? BH[nt >> 1].y : BH[nt >> 1].x;
                unsigned long long bl = (nt & 1) ? BL[nt >> 1].y : BL[nt >> 1].x;
                unsigned bh0 = (unsigned)bh, bh1 = (unsigned)(bh >> 32);
                unsigned bl0 = (unsigned)bl, bl1 = (unsigned)(bl >> 32);
                #pragma unroll
                for (int mt = 0; mt < 2; ++mt) {
                    mma16816(acc[mt][nt], ah[mt], bh0, bh1);   // hi*hi
                    mma16816(acc[mt][nt], al[mt], bh0, bh1);   // lo*hi
                    mma16816(acc[mt][nt], ah[mt], bl0, bl1);   // hi*lo
                }
            }
        }
        __syncthreads();        // reads of cur done -> reuse as out stage

        // out stage: [row][o][mdslot] u64 = (Re,Im), slot = md ^ (o&6)
        #pragma unroll
        for (int mt = 0; mt < 2; ++mt)
            #pragma unroll
            for (int nt = 0; nt < 8; ++nt) {
                int o = nt * 4 + t4;
                unsigned so = (unsigned)(o * 8 + (md ^ (o & 6)));
                int r0 = mt * 16 + gid;
                sts64(cur + (unsigned)(r0 * RS) * 8 + so * 8,
                      pack2(acc[mt][nt][0], acc[mt][nt][1]));
                sts64(cur + (unsigned)((r0 + 8) * RS) * 8 + so * 8,
                      pack2(acc[mt][nt][2], acc[mt][nt][3]));
            }
        __syncthreads();

        // coalesced store: per (row,o) 64B k-run; chunk q -> k = (2q)^(o&6)
        const long trow = rowBase + (long)t * TROWS;
        #pragma unroll
        for (int it = 0; it < 16; ++it) {
            int g = tid + it * THREADS;         // 4096 = (row, o, q)
            int q = g & 3, o = (g >> 2) & 31, row = g >> 7;
            ulonglong2 v = *reinterpret_cast<ulonglong2*>(
                curp + (size_t)(row * RS + o * 8 + q * 2) * 8);
            *reinterpret_cast<ulonglong2*>(
                O + (trow + row) * 4096 + (size_t)o * 128
                  + (size_t)(kg + ((2 * q) ^ (o & 6))) * 2) = v;
        }
        // no extra sync: top-of-next-tile sync orders these reads vs refill
    }
}

extern "C" void kernel_launch(void* const* d_in, const int* in_sizes, int n_in,
                              void* d_out, int out_size)
{
    const float* x = (const float*)d_in[0];   // (8,2048,32,64,2) fp32
    const float* w = (const float*)d_in[1];   // (32,32,64,2) fp32
    float* out = (float*)d_out;               // (8,2048,32,64,2) fp32

    spectral_prepB_kernel<<<8, 256>>>(w);

    cudaFuncSetAttribute(spectral_r14_kernel,
                         cudaFuncAttributeMaxDynamicSharedMemorySize, SMEM_BYTES);
    dim3 grid(16384 / (TROWS * TILES), 64 / KT);   // (128, 8) = 1024 CTAs
    spectral_r14_kernel<<<grid, THREADS, SMEM_BYTES>>>(x, out);
}

// round 16
// speedup vs baseline: 1.0681x; 1.0681x over previous
#include <cuda_runtime.h>
#include <cstdint>

// SpectralConv1d via mma.sync (HMMA) bf16 2-way-split GEMM. Round 16.
// R16 = R15 fixed: gB/B_BYTES sized for the full 64KB-per-kgroup fragment
// set, and corrected cp.async wait discipline.
//  - KT=4 modes/CTA, B fragments in smem (conflict-free LDS.128 inner loop)
//  - kgi-fastest grid: the 4 CTAs writing each 128B O line are wave-adjacent
//  - 16 warps = (mode x row-quarter), m16n64 tile; 64-row double-buffered
//    cp.async pipeline.

#define THREADS 512
#define KT      4
#define TROWS   64                      // rows per tile
#define TILES   4                       // 256 rows per CTA
#define RS      130                     // u64 per stage row
#define BUFB    (TROWS * RS * 8)        // 66560 bytes per buffer
#define NBUF    2
#define B_U64   8192                    // fragments per kgroup (64KB)
#define B_BYTES (B_U64 * 8)
#define SMEM_BYTES (NBUF * BUFB + B_BYTES)   // 198656

__device__ unsigned long long gB[16 * B_U64];   // [kgi][md][s][ks][j][lane]{2u32}

__device__ __forceinline__ unsigned smem_u32(const void* p) {
    unsigned a;
    asm("{ .reg .u64 t; cvta.to.shared.u64 t, %1; cvt.u32.u64 %0, t; }" : "=r"(a) : "l"(p));
    return a;
}
__device__ __forceinline__ unsigned cvt2bf(float lo, float hi) {
    unsigned r;
    asm("cvt.rn.bf16x2.f32 %0, %1, %2;" : "=r"(r) : "f"(hi), "f"(lo));
    return r;
}
__device__ __forceinline__ unsigned long long pack2(float lo, float hi) {
    unsigned long long r;
    asm("mov.b64 %0, {%1, %2};" : "=l"(r) : "f"(lo), "f"(hi));
    return r;
}
__device__ __forceinline__ unsigned long long lds64(unsigned a) {
    unsigned long long v;
    asm volatile("ld.shared.b64 %0, [%1];" : "=l"(v) : "r"(a));
    return v;
}
__device__ __forceinline__ ulonglong2 lds128(unsigned a) {
    ulonglong2 v;
    asm volatile("ld.shared.v2.b64 {%0,%1}, [%2];" : "=l"(v.x), "=l"(v.y) : "r"(a));
    return v;
}
__device__ __forceinline__ void sts64(unsigned a, unsigned long long v) {
    asm volatile("st.shared.b64 [%0], %1;" :: "r"(a), "l"(v));
}
__device__ __forceinline__ void sts128(unsigned a, ulonglong2 v) {
    asm volatile("st.shared.v2.b64 [%0], {%1,%2};" :: "r"(a), "l"(v.x), "l"(v.y));
}
__device__ __forceinline__ void cp_async16(unsigned dst, const void* src) {
    asm volatile("cp.async.cg.shared.global [%0], [%1], 16;\n" :: "r"(dst), "l"(src));
}
__device__ __forceinline__ void cp_commit() { asm volatile("cp.async.commit_group;\n"); }
__device__ __forceinline__ void cp_wait0()  { asm volatile("cp.async.wait_group 0;\n"); }
__device__ __forceinline__ void cp_wait1()  { asm volatile("cp.async.wait_group 1;\n"); }
__device__ __forceinline__ void mma16816(float* c, const unsigned* a,
                                         unsigned b0, unsigned b1) {
    asm volatile(
        "mma.sync.aligned.m16n8k16.row.col.f32.bf16.bf16.f32 "
        "{%0,%1,%2,%3}, {%4,%5,%6,%7}, {%8,%9}, {%0,%1,%2,%3};"
        : "+f"(c[0]), "+f"(c[1]), "+f"(c[2]), "+f"(c[3])
        : "r"(a[0]), "r"(a[1]), "r"(a[2]), "r"(a[3]), "r"(b0), "r"(b1));
}

// ---- prep: B fragments, lane-consecutive layout; 16 kgroups of 4 modes ----
__global__ void __launch_bounds__(256)
spectral_prepB_kernel(const float* __restrict__ W)
{
    const int kgi = blockIdx.x;                 // 0..15
    const int kbase = kgi * KT;
    unsigned* dst = reinterpret_cast<unsigned*>(gB + (size_t)kgi * B_U64);

    #pragma unroll
    for (int it = 0; it < 16; ++it) {
        int idx = threadIdx.x + it * 256;       // 4096 = (o,i,md)
        int md = idx & 3, i = (idx >> 2) & 31, o = idx >> 7;
        float2 wv = *reinterpret_cast<const float2*>(
            W + (size_t)o * 4096 + i * 128 + (size_t)(kbase + md) * 2);
        unsigned ph = cvt2bf(wv.x, wv.y);       // low=wr_h, high=wi_h
        float wrh = __uint_as_float(ph << 16);
        float wih = __uint_as_float(ph & 0xFFFF0000u);
        unsigned pl = cvt2bf(wv.x - wrh, wv.y - wih);
        const int ks = i >> 3, half = (i >> 2) & 1, t4 = i & 3;
        #pragma unroll
        for (int s = 0; s < 2; ++s) {
            unsigned p = s ? pl : ph;
            #pragma unroll
            for (int c = 0; c < 2; ++c) {       // n = 2o + c
                int n = 2 * o + c;
                int gid = n & 7, nt = n >> 3, j = nt >> 1, wsel = nt & 1;
                unsigned u64i =
                    (unsigned)(((((md * 2 + s) * 4 + ks) * 4 + j) * 32
                                + (gid * 4 + t4)) * 2 + wsel);
                unsigned val = c ? ((p >> 16) | (p << 16))    // (wi, wr)
                                 : (p ^ 0x80000000u);         // (wr, -wi)
                dst[u64i * 2 + half] = val;
            }
        }
    }
}

// ---- main ----
__global__ void __launch_bounds__(THREADS, 1)
spectral_r16_kernel(const float* __restrict__ X,
                    float* __restrict__ O)
{
    extern __shared__ char smem[];
    const unsigned sb = smem_u32(smem);
    const unsigned sB = sb + NBUF * BUFB;       // B fragments, 64KB

    const int tid  = threadIdx.x;
    const int lane = tid & 31;
    const int warp = tid >> 5;                  // 0..15
    const int md   = warp & 3;                  // mode
    const int rq   = warp >> 2;                 // row quarter (0..3)
    const int gid  = lane >> 2;
    const int t4   = lane & 3;
    const int kgi  = blockIdx.x;                // kgi FASTEST -> write merge
    const int kg   = kgi * KT;
    const long rowBase = (long)blockIdx.y * (TROWS * TILES);

    // fill tile t: raw fp32 pairs, 16B = 2 modes; slot = (2*md2)^(i&2)
    auto fill = [&](int t) {
        const unsigned buf = sb + (unsigned)(t & 1) * BUFB;
        const float* base = X + (rowBase + (long)t * TROWS) * 4096 + (size_t)kg * 2;
        #pragma unroll
        for (int it = 0; it < 8; ++it) {
            int idx = tid + it * THREADS;       // 4096 = (row, i, md2)
            int md2 = idx & 1, i = (idx >> 1) & 31, row = idx >> 6;
            cp_async16(buf + (unsigned)(row * RS + i * 4 + ((2 * md2) ^ (i & 2))) * 8,
                       base + (size_t)row * 4096 + i * 128 + md2 * 4);
        }
        cp_commit();
    };

    fill(0); fill(1);

    // copy this kgroup's B fragments into smem (8192 u64 = 4096 x 16B)
    {
        const ulonglong2* src =
            reinterpret_cast<const ulonglong2*>(gB + (size_t)kgi * B_U64);
        #pragma unroll
        for (int it = 0; it < 8; ++it) {
            int idx = tid + it * THREADS;       // 4096 chunks
            sts128(sB + (unsigned)idx * 16, src[idx]);
        }
    }

    #pragma unroll 1
    for (int t = 0; t < TILES; ++t) {
        const unsigned cur = sb + (unsigned)(t & 1) * BUFB;
        char* curp = smem + (size_t)(t & 1) * BUFB;

        // fill(t) must be complete (t=0: fill(1) may stay in flight)
        if (t == 0) cp_wait1(); else cp_wait0();
        __syncthreads();    // fill + B copy visible; t-1 store reads done

        // issue next fill into the buffer freed by tile t-1's store phase
        if (t >= 1 && t + 1 < TILES) fill(t + 1);

        float acc[8][4];
        #pragma unroll
        for (int nt = 0; nt < 8; ++nt)
            #pragma unroll
            for (int q = 0; q < 4; ++q) acc[nt][q] = 0.0f;

        #pragma unroll
        for (int ks = 0; ks < 4; ++ks) {
            // B from smem: conflict-free LDS.128 (lane-consecutive 16B)
            ulonglong2 BH[4], BL[4];
            #pragma unroll
            for (int j = 0; j < 4; ++j) {
                BH[j] = lds128(sB + (unsigned)((((md * 2 + 0) * 4 + ks) * 4 + j) * 32
                                               + lane) * 16);
                BL[j] = lds128(sB + (unsigned)((((md * 2 + 1) * 4 + ks) * 4 + j) * 32
                                               + lane) * 16);
            }

            // A: raw fp32 LDS.64 + split-at-use; slot = md ^ (i&2)
            unsigned ah[4], al[4];
            #pragma unroll
            for (int j = 0; j < 4; ++j) {
                int row = rq * 16 + gid + (j & 1) * 8;
                int i   = t4 + (j >> 1) * 4 + 8 * ks;
                unsigned long long v = lds64(
                    cur + (unsigned)(row * RS + i * 4 + (md ^ (i & 2))) * 8);
                float xr, xi;
                asm("mov.b64 {%0,%1}, %2;" : "=f"(xr), "=f"(xi) : "l"(v));
                unsigned ph = cvt2bf(xr, xi);
                float xrh = __uint_as_float(ph << 16);
                float xih = __uint_as_float(ph & 0xFFFF0000u);
                ah[j] = ph;
                al[j] = cvt2bf(xr - xrh, xi - xih);
            }

            #pragma unroll
            for (int nt = 0; nt < 8; ++nt) {
                unsigned long long bh = (nt & 1) ? BH[nt >> 1].y : BH[nt >> 1].x;
                unsigned long long bl = (nt & 1) ? BL[nt >> 1].y : BL[nt >> 1].x;
                mma16816(acc[nt], ah, (unsigned)bh, (unsigned)(bh >> 32)); // hi*hi
                mma16816(acc[nt], al, (unsigned)bh, (unsigned)(bh >> 32)); // lo*hi
                mma16816(acc[nt], ah, (unsigned)bl, (unsigned)(bl >> 32)); // hi*lo
            }
        }
        __syncthreads();        // reads of cur done -> reuse as out stage

        // out stage: [row][o][mdslot] u64 = (Re,Im), slot = md ^ (o&2)
        #pragma unroll
        for (int nt = 0; nt < 8; ++nt) {
            int o = nt * 4 + t4;
            unsigned so = (unsigned)(o * 4 + (md ^ (o & 2)));
            int r0 = rq * 16 + gid;
            sts64(cur + (unsigned)(r0 * RS) * 8 + so * 8,
                  pack2(acc[nt][0], acc[nt][1]));
            sts64(cur + (unsigned)((r0 + 8) * RS) * 8 + so * 8,
                  pack2(acc[nt][2], acc[nt][3]));
        }
        __syncthreads();

        // store: per (row,o) 32B k-run; chunk q -> mode pair p = q ^ ((o>>1)&1)
        const long trow = rowBase + (long)t * TROWS;
        #pragma unroll
        for (int it = 0; it < 8; ++it) {
            int g = tid + it * THREADS;         // 4096 = (row, o, q)
            int q = g & 1, o = (g >> 1) & 31, row = g >> 6;
            ulonglong2 v = *reinterpret_cast<ulonglong2*>(
                curp + (size_t)(row * RS + o * 4 + q * 2) * 8);
            int p = q ^ ((o >> 1) & 1);
            *reinterpret_cast<ulonglong2*>(
                O + (trow + row) * 4096 + (size_t)o * 128
                  + (size_t)(kg + 2 * p) * 2) = v;
        }
        // next-tile top sync orders these reads vs refill of this buffer
    }
}

extern "C" void kernel_launch(void* const* d_in, const int* in_sizes, int n_in,
                              void* d_out, int out_size)
{
    const float* x = (const float*)d_in[0];   // (8,2048,32,64,2) fp32
    const float* w = (const float*)d_in[1];   // (32,32,64,2) fp32
    float* out = (float*)d_out;               // (8,2048,32,64,2) fp32

    spectral_prepB_kernel<<<16, 256>>>(w);

    cudaFuncSetAttribute(spectral_r16_kernel,
                         cudaFuncAttributeMaxDynamicSharedMemorySize, SMEM_BYTES);
    // kgi fastest: the 4 CTAs writing each 128B output line are adjacent bids
    dim3 grid(16, 16384 / (TROWS * TILES));   // (16 kgi, 16 rowgroups)
    spectral_r16_kernel<<<grid, THREADS, SMEM_BYTES>>>(x, out);
}

// round 17
// speedup vs baseline: 1.0803x; 1.0114x over previous
#include <cuda_runtime.h>
#include <cstdint>

// SpectralConv1d via mma.sync (HMMA) bf16 2-way-split GEMM. Round 17.
// R17: 2 CTAs/SM (256 thr, <=128 regs, 96.5KB smem) for cross-CTA phase
//      overlap; warp = (mode, n-half) so B fragment loads have ZERO
//      redundancy; KT=4, B in smem, kgi-fastest grid, 16-row cp.async ring.

#define THREADS 256
#define KT      4
#define TROWS   16                      // rows per tile
#define TILES   8                       // 128 rows per CTA
#define RS      130                     // u64 per stage row
#define BUFB    (TROWS * RS * 8)        // 16640 bytes per buffer
#define NBUF    2
#define B_U64   8192                    // fragments per kgroup (64KB)
#define B_BYTES (B_U64 * 8)
#define SMEM_BYTES (NBUF * BUFB + B_BYTES)   // 98816

__device__ unsigned long long gB[16 * B_U64];   // [kgi][md][s][ks][j][lane]{2u32}

__device__ __forceinline__ unsigned smem_u32(const void* p) {
    unsigned a;
    asm("{ .reg .u64 t; cvta.to.shared.u64 t, %1; cvt.u32.u64 %0, t; }" : "=r"(a) : "l"(p));
    return a;
}
__device__ __forceinline__ unsigned cvt2bf(float lo, float hi) {
    unsigned r;
    asm("cvt.rn.bf16x2.f32 %0, %1, %2;" : "=r"(r) : "f"(hi), "f"(lo));
    return r;
}
__device__ __forceinline__ unsigned long long pack2(float lo, float hi) {
    unsigned long long r;
    asm("mov.b64 %0, {%1, %2};" : "=l"(r) : "f"(lo), "f"(hi));
    return r;
}
__device__ __forceinline__ unsigned long long lds64(unsigned a) {
    unsigned long long v;
    asm volatile("ld.shared.b64 %0, [%1];" : "=l"(v) : "r"(a));
    return v;
}
__device__ __forceinline__ ulonglong2 lds128(unsigned a) {
    ulonglong2 v;
    asm volatile("ld.shared.v2.b64 {%0,%1}, [%2];" : "=l"(v.x), "=l"(v.y) : "r"(a));
    return v;
}
__device__ __forceinline__ void sts64(unsigned a, unsigned long long v) {
    asm volatile("st.shared.b64 [%0], %1;" :: "r"(a), "l"(v));
}
__device__ __forceinline__ void sts128(unsigned a, ulonglong2 v) {
    asm volatile("st.shared.v2.b64 [%0], {%1,%2};" :: "r"(a), "l"(v.x), "l"(v.y));
}
__device__ __forceinline__ void cp_async16(unsigned dst, const void* src) {
    asm volatile("cp.async.cg.shared.global [%0], [%1], 16;\n" :: "r"(dst), "l"(src));
}
__device__ __forceinline__ void cp_commit() { asm volatile("cp.async.commit_group;\n"); }
__device__ __forceinline__ void cp_wait0()  { asm volatile("cp.async.wait_group 0;\n"); }
__device__ __forceinline__ void cp_wait1()  { asm volatile("cp.async.wait_group 1;\n"); }
__device__ __forceinline__ void mma16816(float* c, const unsigned* a,
                                         unsigned b0, unsigned b1) {
    asm volatile(
        "mma.sync.aligned.m16n8k16.row.col.f32.bf16.bf16.f32 "
        "{%0,%1,%2,%3}, {%4,%5,%6,%7}, {%8,%9}, {%0,%1,%2,%3};"
        : "+f"(c[0]), "+f"(c[1]), "+f"(c[2]), "+f"(c[3])
        : "r"(a[0]), "r"(a[1]), "r"(a[2]), "r"(a[3]), "r"(b0), "r"(b1));
}

// ---- prep: B fragments, lane-consecutive layout; 16 kgroups of 4 modes ----
__global__ void __launch_bounds__(256)
spectral_prepB_kernel(const float* __restrict__ W)
{
    const int kgi = blockIdx.x;                 // 0..15
    const int kbase = kgi * KT;
    unsigned* dst = reinterpret_cast<unsigned*>(gB + (size_t)kgi * B_U64);

    #pragma unroll
    for (int it = 0; it < 16; ++it) {
        int idx = threadIdx.x + it * 256;       // 4096 = (o,i,md)
        int md = idx & 3, i = (idx >> 2) & 31, o = idx >> 7;
        float2 wv = *reinterpret_cast<const float2*>(
            W + (size_t)o * 4096 + i * 128 + (size_t)(kbase + md) * 2);
        unsigned ph = cvt2bf(wv.x, wv.y);       // low=wr_h, high=wi_h
        float wrh = __uint_as_float(ph << 16);
        float wih = __uint_as_float(ph & 0xFFFF0000u);
        unsigned pl = cvt2bf(wv.x - wrh, wv.y - wih);
        const int ks = i >> 3, half = (i >> 2) & 1, t4 = i & 3;
        #pragma unroll
        for (int s = 0; s < 2; ++s) {
            unsigned p = s ? pl : ph;
            #pragma unroll
            for (int c = 0; c < 2; ++c) {       // n = 2o + c
                int n = 2 * o + c;
                int gid = n & 7, nt = n >> 3, j = nt >> 1, wsel = nt & 1;
                unsigned u64i =
                    (unsigned)(((((md * 2 + s) * 4 + ks) * 4 + j) * 32
                                + (gid * 4 + t4)) * 2 + wsel);
                unsigned val = c ? ((p >> 16) | (p << 16))    // (wi, wr)
                                 : (p ^ 0x80000000u);         // (wr, -wi)
                dst[u64i * 2 + half] = val;
            }
        }
    }
}

// ---- main ----
__global__ void __launch_bounds__(THREADS, 2)
spectral_r17_kernel(const float* __restrict__ X,
                    float* __restrict__ O)
{
    extern __shared__ char smem[];
    const unsigned sb = smem_u32(smem);
    const unsigned sB = sb + NBUF * BUFB;       // B fragments, 64KB

    const int tid  = threadIdx.x;
    const int lane = tid & 31;
    const int warp = tid >> 5;                  // 0..7
    const int md   = warp & 3;                  // mode
    const int nh   = warp >> 2;                 // n-half (0/1): n in [nh*32, nh*32+32)
    const int gid  = lane >> 2;
    const int t4   = lane & 3;
    const int kgi  = blockIdx.x;                // kgi FASTEST -> L2 line sharing
    const int kg   = kgi * KT;
    const long rowBase = (long)blockIdx.y * (TROWS * TILES);

    // fill tile t: raw fp32 pairs, 16B = 2 modes; slot = (2*md2)^(i&2)
    auto fill = [&](int t) {
        const unsigned buf = sb + (unsigned)(t & 1) * BUFB;
        const float* base = X + (rowBase + (long)t * TROWS) * 4096 + (size_t)kg * 2;
        #pragma unroll
        for (int it = 0; it < 4; ++it) {
            int idx = tid + it * THREADS;       // 1024 = (row, i, md2)
            int md2 = idx & 1, i = (idx >> 1) & 31, row = idx >> 6;
            cp_async16(buf + (unsigned)(row * RS + i * 4 + ((2 * md2) ^ (i & 2))) * 8,
                       base + (size_t)row * 4096 + i * 128 + md2 * 4);
        }
        cp_commit();
    };

    fill(0); fill(1);

    // copy this kgroup's B fragments into smem (8192 u64 = 4096 x 16B)
    {
        const ulonglong2* src =
            reinterpret_cast<const ulonglong2*>(gB + (size_t)kgi * B_U64);
        #pragma unroll
        for (int it = 0; it < 16; ++it) {
            int idx = tid + it * THREADS;
            sts128(sB + (unsigned)idx * 16, src[idx]);
        }
    }

    #pragma unroll 1
    for (int t = 0; t < TILES; ++t) {
        const unsigned cur = sb + (unsigned)(t & 1) * BUFB;
        char* curp = smem + (size_t)(t & 1) * BUFB;

        // fill(t) must be complete (t=0: fill(1) may stay in flight)
        if (t == 0) cp_wait1(); else cp_wait0();
        __syncthreads();    // fill + B copy visible; t-1 store reads done

        if (t >= 1 && t + 1 < TILES) fill(t + 1);

        float acc[4][4];
        #pragma unroll
        for (int nt = 0; nt < 4; ++nt)
            #pragma unroll
            for (int q = 0; q < 4; ++q) acc[nt][q] = 0.0f;

        #pragma unroll
        for (int ks = 0; ks < 4; ++ks) {
            // B from smem: this warp's n-half only (zero redundancy)
            // j = nh*2 + jj, jj in {0,1}
            ulonglong2 BH[2], BL[2];
            #pragma unroll
            for (int jj = 0; jj < 2; ++jj) {
                int j = nh * 2 + jj;
                BH[jj] = lds128(sB + (unsigned)((((md * 2 + 0) * 4 + ks) * 4 + j) * 32
                                                + lane) * 16);
                BL[jj] = lds128(sB + (unsigned)((((md * 2 + 1) * 4 + ks) * 4 + j) * 32
                                                + lane) * 16);
            }

            // A: raw fp32 LDS.64 + split-at-use; slot = md ^ (i&2)
            unsigned ah[4], al[4];
            #pragma unroll
            for (int j = 0; j < 4; ++j) {
                int row = gid + (j & 1) * 8;
                int i   = t4 + (j >> 1) * 4 + 8 * ks;
                unsigned long long v = lds64(
                    cur + (unsigned)(row * RS + i * 4 + (md ^ (i & 2))) * 8);
                float xr, xi;
                asm("mov.b64 {%0,%1}, %2;" : "=f"(xr), "=f"(xi) : "l"(v));
                unsigned ph = cvt2bf(xr, xi);
                float xrh = __uint_as_float(ph << 16);
                float xih = __uint_as_float(ph & 0xFFFF0000u);
                ah[j] = ph;
                al[j] = cvt2bf(xr - xrh, xi - xih);
            }

            #pragma unroll
            for (int nt = 0; nt < 4; ++nt) {
                unsigned long long bh = (nt & 1) ? BH[nt >> 1].y : BH[nt >> 1].x;
                unsigned long long bl = (nt & 1) ? BL[nt >> 1].y : BL[nt >> 1].x;
                mma16816(acc[nt], ah, (unsigned)bh, (unsigned)(bh >> 32)); // hi*hi
                mma16816(acc[nt], al, (unsigned)bh, (unsigned)(bh >> 32)); // lo*hi
                mma16816(acc[nt], ah, (unsigned)bl, (unsigned)(bl >> 32)); // hi*lo
            }
        }
        __syncthreads();        // reads of cur done -> reuse as out stage

        // out stage: [row][o][mdslot] u64 = (Re,Im), slot = md ^ (o&2)
        // lane's o = (nh*4 + nt)*4 + t4
        #pragma unroll
        for (int nt = 0; nt < 4; ++nt) {
            int o = (nh * 4 + nt) * 4 + t4;
            unsigned so = (unsigned)(o * 4 + (md ^ (o & 2)));
            sts64(cur + (unsigned)(gid * RS) * 8 + so * 8,
                  pack2(acc[nt][0], acc[nt][1]));
            sts64(cur + (unsigned)((gid + 8) * RS) * 8 + so * 8,
                  pack2(acc[nt][2], acc[nt][3]));
        }
        __syncthreads();

        // store: per (row,o) 32B k-run; chunk q -> mode pair p = q ^ ((o>>1)&1)
        const long trow = rowBase + (long)t * TROWS;
        #pragma unroll
        for (int it = 0; it < 4; ++it) {
            int g = tid + it * THREADS;         // 1024 = (row, o, q)
            int q = g & 1, o = (g >> 1) & 31, row = g >> 6;
            ulonglong2 v = *reinterpret_cast<ulonglong2*>(
                curp + (size_t)(row * RS + o * 4 + q * 2) * 8);
            int p = q ^ ((o >> 1) & 1);
            *reinterpret_cast<ulonglong2*>(
                O + (trow + row) * 4096 + (size_t)o * 128
                  + (size_t)(kg + 2 * p) * 2) = v;
        }
        // next-tile top sync orders these reads vs refill of this buffer
    }
}

extern "C" void kernel_launch(void* const* d_in, const int* in_sizes, int n_in,
                              void* d_out, int out_size)
{
    const float* x = (const float*)d_in[0];   // (8,2048,32,64,2) fp32
    const float* w = (const float*)d_in[1];   // (32,32,64,2) fp32
    float* out = (float*)d_out;               // (8,2048,32,64,2) fp32

    spectral_prepB_kernel<<<16, 256>>>(w);

    cudaFuncSetAttribute(spectral_r17_kernel,
                         cudaFuncAttributeMaxDynamicSharedMemorySize, SMEM_BYTES);
    // kgi fastest: CTAs sharing X/O lines are wave-adjacent
    dim3 grid(16, 16384 / (TROWS * TILES));   // (16 kgi, 128 rowgroups)
    spectral_r17_kernel<<<grid, THREADS, SMEM_BYTES>>>(x, out);
}